// round 14
// baseline (speedup 1.0000x reference)
#include <cuda_runtime.h>

#define SS 512
#define NUNITS 9
#define DSTRIDE 520   // 512 data + 8 zero pad; 130 float4 per row
#define MAXB 128

__device__ float g_diag[MAXB * DSTRIDE];
__device__ float g_bias[SS * SS];

// Fused prep: diag gather (MLP=4 per thread) on low blocks; bias reduction via
// coalesced float4 -> smem -> conflict-free scalar reads (9t+i mod 32).
__global__ void prep_kernel(const float* __restrict__ in,
                            const float* __restrict__ bb,
                            int B, int ndiag_blocks) {
    __shared__ float sb[256 * 9];
    if (blockIdx.x < (unsigned)ndiag_blocks) {
        int idx = blockIdx.x * blockDim.x + threadIdx.x;
        int bq = idx / DSTRIDE;
        int j  = idx - bq * DSTRIDE;
        int b4 = bq * 4;
        if (b4 >= B) return;
        float v[4] = {0.f, 0.f, 0.f, 0.f};
        bool jin = (j < SS);
#pragma unroll
        for (int k = 0; k < 4; k++) {
            if (jin && b4 + k < B)
                v[k] = __ldg(in + (size_t)(b4 + k) * SS * SS + (size_t)j * (SS + 1));
        }
#pragma unroll
        for (int k = 0; k < 4; k++) {
            if (b4 + k < B) g_diag[(size_t)(b4 + k) * DSTRIDE + j] = v[k];
        }
    } else {
        int tid = threadIdx.x;
        int out0 = (blockIdx.x - ndiag_blocks) * 256;
        const float4* src = (const float4*)(bb + (size_t)out0 * 9);
        float4* s4 = (float4*)sb;
#pragma unroll
        for (int r = 0; r < 3; r++) {
            int k = tid + r * 256;
            if (k < 576) s4[k] = src[k];
        }
        __syncthreads();
        float acc = 0.0f;
#pragma unroll
        for (int t = 0; t < 9; t++) acc += sb[tid * 9 + t];
        g_bias[out0 + tid] = acc;
    }
}

// Main kernel: 2 i-rows per thread (diag window shared -> 3 LDG feed 8
// outputs) + batch-phase rotation + PDL. 20 warps/SM at reg cap 100.
__global__ __launch_bounds__(128, 5)
void cnn_kernel(const float* __restrict__ w,
                float* __restrict__ out,
                int B, int bper) {
    int i0 = blockIdx.x * 2;      // 0,2,...,510
    int i1 = i0 + 1;
    int j0 = threadIdx.x << 2;    // 0,4,...,508
    int b0 = blockIdx.y * bper;
    int b1 = b0 + bper;
    if (b1 > B) b1 = B;
    if (b0 >= b1) { cudaGridDependencySynchronize(); return; }
    int nb = b1 - b0;

    // ---- prologue (independent of prep): 18x LDG.128 weights ----
    float wa[36], wb[36];
    const float4* wpa = (const float4*)(w + ((size_t)i0 * SS + j0) * NUNITS);
    const float4* wpb = (const float4*)(w + ((size_t)i1 * SS + j0) * NUNITS);
#pragma unroll
    for (int k = 0; k < 9; k++) {
        float4 qa = wpa[k];
        wa[k * 4 + 0] = qa.x; wa[k * 4 + 1] = qa.y;
        wa[k * 4 + 2] = qa.z; wa[k * 4 + 3] = qa.w;
        float4 qb = wpb[k];
        wb[k * 4 + 0] = qb.x; wb[k * 4 + 1] = qb.y;
        wb[k * 4 + 2] = qb.z; wb[k * 4 + 3] = qb.w;
    }
#pragma unroll
    for (int n = 0; n < 36; n++) {
        int t = n % 9;                          // compile-time per n
        wa[n] *= (i0 + (t / 3) < SS) ? 9.0f : 0.0f;
        wb[n] *= (i1 + (t / 3) < SS) ? 9.0f : 0.0f;
    }

    // ---- wait for prep results ----
    cudaGridDependencySynchronize();

    float4 biasa = *(const float4*)(g_bias + (size_t)i0 * SS + j0);
    float4 biasb = *(const float4*)(g_bias + (size_t)i1 * SS + j0);

    const float* dbase = g_diag + (size_t)b0 * DSTRIDE + j0;
    float* obase = out + (size_t)b0 * (SS * SS) + (size_t)i0 * SS + j0;

    // rotation phase: decorrelate rows across blocks
    int idx = (int)((blockIdx.x * 7 + blockIdx.y * 3) % nb);

    for (int lb = 0; lb < nb; ++lb) {
        const float4* dq = (const float4*)(dbase + (size_t)idx * DSTRIDE);
        float4 c0 = dq[0], c1 = dq[1], c2 = dq[2];
        float d[12] = {c0.x, c0.y, c0.z, c0.w,
                       c1.x, c1.y, c1.z, c1.w,
                       c2.x, c2.y, c2.z, c2.w};

        float a0 = biasa.x, a1 = biasa.y, a2 = biasa.z, a3 = biasa.w;
        float e0 = biasb.x, e1 = biasb.y, e2 = biasb.z, e3 = biasb.w;
#pragma unroll
        for (int t = 0; t < 9; t++) {
            a0 = fmaf(d[t],     wa[t],      a0);
            a1 = fmaf(d[t + 1], wa[9 + t],  a1);
            a2 = fmaf(d[t + 2], wa[18 + t], a2);
            a3 = fmaf(d[t + 3], wa[27 + t], a3);
            e0 = fmaf(d[t],     wb[t],      e0);
            e1 = fmaf(d[t + 1], wb[9 + t],  e1);
            e2 = fmaf(d[t + 2], wb[18 + t], e2);
            e3 = fmaf(d[t + 3], wb[27 + t], e3);
        }
        float* op = obase + (size_t)idx * (SS * SS);
        float4 oa; oa.x = a0; oa.y = a1; oa.z = a2; oa.w = a3;
        float4 ob; ob.x = e0; ob.y = e1; ob.z = e2; ob.w = e3;
        __stcs((float4*)op,        oa);
        __stcs((float4*)(op + SS), ob);

        ++idx;
        idx = (idx == nb) ? 0 : idx;            // branch-free wrap
    }
}

extern "C" void kernel_launch(void* const* d_in, const int* in_sizes, int n_in,
                              void* d_out, int out_size) {
    const float* in = (const float*)d_in[0];   // inputs (B,512,512,1) f32
    const float* w  = (const float*)d_in[1];   // w (512*512*9,) f32
    const float* bb = (const float*)d_in[2];   // b (512*512*9,) f32
    float* out = (float*)d_out;                // (B, 512*512) f32

    int B = in_sizes[0] / (SS * SS);
    if (B > MAXB) B = MAXB;

    {
        int bq = (B + 3) / 4;
        int ndiag_blocks = (bq * DSTRIDE + 255) / 256;   // ~51
        int nbias_blocks = (SS * SS) / 256;              // 1024
        prep_kernel<<<ndiag_blocks + nbias_blocks, 256>>>(in, bb, B, ndiag_blocks);
    }

    const int NSLICE = 8;                      // 2048 blocks ~= 2.77 waves @ 5/SM
    int bper = (B + NSLICE - 1) / NSLICE;      // 13
    dim3 grid(SS / 2, NSLICE);                 // 256 x 8

    cudaLaunchConfig_t cfg = {};
    cfg.gridDim = grid;
    cfg.blockDim = dim3(128, 1, 1);
    cfg.dynamicSmemBytes = 0;
    cfg.stream = 0;
    cudaLaunchAttribute attrs[1];
    attrs[0].id = cudaLaunchAttributeProgrammaticStreamSerialization;
    attrs[0].val.programmaticStreamSerializationAllowed = 1;
    cfg.attrs = attrs;
    cfg.numAttrs = 1;
    cudaError_t e = cudaLaunchKernelEx(&cfg, cnn_kernel, w, out, B, bper);
    if (e != cudaSuccess) {
        cnn_kernel<<<grid, 128>>>(w, out, B, bper);
    }
}

// round 15
// speedup vs baseline: 1.0473x; 1.0473x over previous
#include <cuda_runtime.h>

#define SS 512
#define NUNITS 9
#define DSTRIDE 520   // 512 data + 8 zero pad; 130 float4 per row
#define MAXB 128

__device__ float g_diag[MAXB * DSTRIDE];

// Prep: diag gather only (MLP=4 per thread). Bias reduction moved into the
// cnn prologue (pre-sync, PDL-overlapped), so prep is ~1.3us and fully hidden.
__global__ void prep_kernel(const float* __restrict__ in, int B) {
    int idx = blockIdx.x * blockDim.x + threadIdx.x;
    int bq = idx / DSTRIDE;
    int j  = idx - bq * DSTRIDE;
    int b4 = bq * 4;
    if (b4 >= B) return;
    float v[4] = {0.f, 0.f, 0.f, 0.f};
    bool jin = (j < SS);
#pragma unroll
    for (int k = 0; k < 4; k++) {
        if (jin && b4 + k < B)
            v[k] = __ldg(in + (size_t)(b4 + k) * SS * SS + (size_t)j * (SS + 1));
    }
#pragma unroll
    for (int k = 0; k < 4; k++) {
        if (b4 + k < B) g_diag[(size_t)(b4 + k) * DSTRIDE + j] = v[k];
    }
}

// Main kernel (R13 shape): thread owns (i, j0..j0+3) and a batch slice;
// 36 masked*9 weights + 4 bias sums in registers; batch-phase rotation;
// per iter 3x LDG.128 + 36 FMA + 1x STG.128 (streaming). 7 blocks/SM.
// Pre-sync prologue loads BOTH w and b (bias summed on the fly), overlapping
// the diag-gather prep via PDL.
__global__ __launch_bounds__(128, 7)
void cnn_kernel(const float* __restrict__ w,
                const float* __restrict__ bb,
                float* __restrict__ out,
                int B, int bper) {
    int i  = blockIdx.x;          // 0..511
    int j0 = threadIdx.x << 2;    // 0,4,...,508
    int b0 = blockIdx.y * bper;
    int b1 = b0 + bper;
    if (b1 > B) b1 = B;
    if (b0 >= b1) { cudaGridDependencySynchronize(); return; }
    int nb = b1 - b0;

    // ---- prologue (independent of prep): 9x LDG.128 w + 9x LDG.128 b ----
    float bx = 0.f, by = 0.f, bz = 0.f, bw = 0.f;
    {
        const float4* bp4 = (const float4*)(bb + ((size_t)i * SS + j0) * NUNITS);
#pragma unroll
        for (int k = 0; k < 9; k++) {
            float4 q = bp4[k];
            // element n = 4k+c belongs to output jj = n/9 (compile-time)
            float* acc[4] = {&bx, &by, &bz, &bw};
            *acc[(4 * k + 0) / 9] += q.x;
            *acc[(4 * k + 1) / 9] += q.y;
            *acc[(4 * k + 2) / 9] += q.z;
            *acc[(4 * k + 3) / 9] += q.w;
        }
    }

    float wv[36];
    const float4* wp4 = (const float4*)(w + ((size_t)i * SS + j0) * NUNITS);
#pragma unroll
    for (int k = 0; k < 9; k++) {
        float4 q = wp4[k];
        wv[k * 4 + 0] = q.x; wv[k * 4 + 1] = q.y;
        wv[k * 4 + 2] = q.z; wv[k * 4 + 3] = q.w;
    }
#pragma unroll
    for (int n = 0; n < 36; n++) {
        int t = n % 9;                          // compile-time per n
        wv[n] *= (i + (t / 3) < SS) ? 9.0f : 0.0f;
    }

    // ---- wait for prep (diag) ----
    cudaGridDependencySynchronize();

    const float* dbase = g_diag + (size_t)b0 * DSTRIDE + j0;
    float* obase = out + (size_t)b0 * (SS * SS) + (size_t)i * SS + j0;

    // rotation phase: decorrelate rows across blocks
    int idx = (blockIdx.x * 7) % nb;

    for (int lb = 0; lb < nb; ++lb) {
        const float4* dq = (const float4*)(dbase + (size_t)idx * DSTRIDE);
        float4 c0 = dq[0], c1 = dq[1], c2 = dq[2];
        float d[12] = {c0.x, c0.y, c0.z, c0.w,
                       c1.x, c1.y, c1.z, c1.w,
                       c2.x, c2.y, c2.z, c2.w};

        float s0 = bx, s1 = by, s2 = bz, s3 = bw;
#pragma unroll
        for (int t = 0; t < 9; t++) {
            s0 = fmaf(d[t],     wv[t],      s0);
            s1 = fmaf(d[t + 1], wv[9 + t],  s1);
            s2 = fmaf(d[t + 2], wv[18 + t], s2);
            s3 = fmaf(d[t + 3], wv[27 + t], s3);
        }
        float4 o; o.x = s0; o.y = s1; o.z = s2; o.w = s3;
        __stcs((float4*)(obase + (size_t)idx * (SS * SS)), o);

        ++idx;
        idx = (idx == nb) ? 0 : idx;            // branch-free wrap
    }
}

extern "C" void kernel_launch(void* const* d_in, const int* in_sizes, int n_in,
                              void* d_out, int out_size) {
    const float* in = (const float*)d_in[0];   // inputs (B,512,512,1) f32
    const float* w  = (const float*)d_in[1];   // w (512*512*9,) f32
    const float* bb = (const float*)d_in[2];   // b (512*512*9,) f32
    float* out = (float*)d_out;                // (B, 512*512) f32

    int B = in_sizes[0] / (SS * SS);
    if (B > MAXB) B = MAXB;

    {
        int bq = (B + 3) / 4;
        int ndiag_blocks = (bq * DSTRIDE + 255) / 256;   // ~51
        prep_kernel<<<ndiag_blocks, 256>>>(in, B);
    }

    const int NSLICE = 6;                      // 3072 blocks ~= 2.97 waves @ 7/SM
    int bper = (B + NSLICE - 1) / NSLICE;      // 17
    dim3 grid(SS, NSLICE);

    cudaLaunchConfig_t cfg = {};
    cfg.gridDim = grid;
    cfg.blockDim = dim3(128, 1, 1);
    cfg.dynamicSmemBytes = 0;
    cfg.stream = 0;
    cudaLaunchAttribute attrs[1];
    attrs[0].id = cudaLaunchAttributeProgrammaticStreamSerialization;
    attrs[0].val.programmaticStreamSerializationAllowed = 1;
    cfg.attrs = attrs;
    cfg.numAttrs = 1;
    cudaError_t e = cudaLaunchKernelEx(&cfg, cnn_kernel, w, bb, out, B, bper);
    if (e != cudaSuccess) {
        cnn_kernel<<<grid, 128>>>(w, bb, out, B, bper);
    }
}

// round 16
// speedup vs baseline: 1.2718x; 1.2144x over previous
#include <cuda_runtime.h>

#define SS 512
#define NUNITS 9
#define DSTRIDE 544   // 512 data + 32 zero pad; 2176 B row pitch = 17 x 128B
#define MAXB 128

__device__ __align__(256) float g_diag[MAXB * DSTRIDE];
__device__ float g_bias[SS * SS];

// Fused prep: diag gather (MLP=4 per thread) on low blocks; bias reduction via
// coalesced float4 -> smem -> conflict-free scalar reads (9t+i mod 32).
__global__ void prep_kernel(const float* __restrict__ in,
                            const float* __restrict__ bb,
                            int B, int ndiag_blocks) {
    __shared__ float sb[256 * 9];
    if (blockIdx.x < (unsigned)ndiag_blocks) {
        int idx = blockIdx.x * blockDim.x + threadIdx.x;
        int bq = idx / DSTRIDE;
        int j  = idx - bq * DSTRIDE;
        int b4 = bq * 4;
        if (b4 >= B) return;
        float v[4] = {0.f, 0.f, 0.f, 0.f};
        bool jin = (j < SS);
#pragma unroll
        for (int k = 0; k < 4; k++) {
            if (jin && b4 + k < B)
                v[k] = __ldg(in + (size_t)(b4 + k) * SS * SS + (size_t)j * (SS + 1));
        }
#pragma unroll
        for (int k = 0; k < 4; k++) {
            if (b4 + k < B) g_diag[(size_t)(b4 + k) * DSTRIDE + j] = v[k];
        }
    } else {
        int tid = threadIdx.x;
        int out0 = (blockIdx.x - ndiag_blocks) * 256;
        const float4* src = (const float4*)(bb + (size_t)out0 * 9);
        float4* s4 = (float4*)sb;
#pragma unroll
        for (int r = 0; r < 3; r++) {
            int k = tid + r * 256;
            if (k < 576) s4[k] = src[k];
        }
        __syncthreads();
        float acc = 0.0f;
#pragma unroll
        for (int t = 0; t < 9; t++) acc += sb[tid * 9 + t];
        g_bias[out0 + tid] = acc;
    }
}

// Main kernel (R13 shape, line-aligned diag rows): thread owns (i, j0..j0+3)
// and a batch slice; batch-phase rotation; per iter 3x LDG.128 + 36 FMA +
// 1x STG.128 (streaming). 72 regs -> 7 blocks/SM (28 warps).
__global__ __launch_bounds__(128, 7)
void cnn_kernel(const float* __restrict__ w,
                float* __restrict__ out,
                int B, int bper) {
    int i  = blockIdx.x;          // 0..511
    int j0 = threadIdx.x << 2;    // 0,4,...,508
    int b0 = blockIdx.y * bper;
    int b1 = b0 + bper;
    if (b1 > B) b1 = B;
    if (b0 >= b1) { cudaGridDependencySynchronize(); return; }
    int nb = b1 - b0;

    // ---- prologue (independent of prep): 9x LDG.128 weights ----
    float wv[36];
    const float4* wp4 = (const float4*)(w + ((size_t)i * SS + j0) * NUNITS);
#pragma unroll
    for (int k = 0; k < 9; k++) {
        float4 q = wp4[k];
        wv[k * 4 + 0] = q.x; wv[k * 4 + 1] = q.y;
        wv[k * 4 + 2] = q.z; wv[k * 4 + 3] = q.w;
    }
#pragma unroll
    for (int n = 0; n < 36; n++) {
        int t = n % 9;                          // compile-time per n
        wv[n] *= (i + (t / 3) < SS) ? 9.0f : 0.0f;
    }

    // ---- wait for prep results ----
    cudaGridDependencySynchronize();

    float4 bias4 = *(const float4*)(g_bias + (size_t)i * SS + j0);

    const float* dbase = g_diag + (size_t)b0 * DSTRIDE + j0;
    float* obase = out + (size_t)b0 * (SS * SS) + (size_t)i * SS + j0;

    // rotation phase: decorrelate rows across blocks
    int idx = (blockIdx.x * 7) % nb;

    for (int lb = 0; lb < nb; ++lb) {
        const float4* dq = (const float4*)(dbase + (size_t)idx * DSTRIDE);
        float4 c0 = dq[0], c1 = dq[1], c2 = dq[2];
        float d[12] = {c0.x, c0.y, c0.z, c0.w,
                       c1.x, c1.y, c1.z, c1.w,
                       c2.x, c2.y, c2.z, c2.w};

        float s0 = bias4.x, s1 = bias4.y, s2 = bias4.z, s3 = bias4.w;
#pragma unroll
        for (int t = 0; t < 9; t++) {
            s0 = fmaf(d[t],     wv[t],      s0);
            s1 = fmaf(d[t + 1], wv[9 + t],  s1);
            s2 = fmaf(d[t + 2], wv[18 + t], s2);
            s3 = fmaf(d[t + 3], wv[27 + t], s3);
        }
        float4 o; o.x = s0; o.y = s1; o.z = s2; o.w = s3;
        __stcs((float4*)(obase + (size_t)idx * (SS * SS)), o);

        ++idx;
        idx = (idx == nb) ? 0 : idx;            // branch-free wrap
    }
}

extern "C" void kernel_launch(void* const* d_in, const int* in_sizes, int n_in,
                              void* d_out, int out_size) {
    const float* in = (const float*)d_in[0];   // inputs (B,512,512,1) f32
    const float* w  = (const float*)d_in[1];   // w (512*512*9,) f32
    const float* bb = (const float*)d_in[2];   // b (512*512*9,) f32
    float* out = (float*)d_out;                // (B, 512*512) f32

    int B = in_sizes[0] / (SS * SS);
    if (B > MAXB) B = MAXB;

    {
        int bq = (B + 3) / 4;
        int ndiag_blocks = (bq * DSTRIDE + 255) / 256;   // ~54
        int nbias_blocks = (SS * SS) / 256;              // 1024
        prep_kernel<<<ndiag_blocks + nbias_blocks, 256>>>(in, bb, B, ndiag_blocks);
    }

    const int NSLICE = 6;                      // 3072 blocks ~= 2.97 waves @ 7/SM
    int bper = (B + NSLICE - 1) / NSLICE;      // 17
    dim3 grid(SS, NSLICE);

    cudaLaunchConfig_t cfg = {};
    cfg.gridDim = grid;
    cfg.blockDim = dim3(128, 1, 1);
    cfg.dynamicSmemBytes = 0;
    cfg.stream = 0;
    cudaLaunchAttribute attrs[1];
    attrs[0].id = cudaLaunchAttributeProgrammaticStreamSerialization;
    attrs[0].val.programmaticStreamSerializationAllowed = 1;
    cfg.attrs = attrs;
    cfg.numAttrs = 1;
    cudaError_t e = cudaLaunchKernelEx(&cfg, cnn_kernel, w, out, B, bper);
    if (e != cudaSuccess) {
        cnn_kernel<<<grid, 128>>>(w, out, B, bper);
    }
}